// round 5
// baseline (speedup 1.0000x reference)
#include <cuda_runtime.h>

#define BN 4096
#define DN 128
#define MN 8192
#define KS 4
#define QN (2*BN*DN)
#define HALFQ (BN*DN)
#define OFF_LOSS 1048576
#define OFF_IDS  1048577
#define OFF_PERP 1081345

typedef unsigned long long ull;

// ---------- device scratch (no allocations allowed) ----------
__device__ float g_Enorm[KS*MN];
__device__ float g_xnorm0[2*BN];
__device__ float g_xnormR[2*BN];
__device__ float g_res[QN];
__device__ float g_q[QN];
__device__ ull   g_min[2*BN];
__device__ int   g_counts[KS*2*MN];
__device__ int   g_idx[2*BN*KS];
__device__ float g_ph[2ull*BN*MN];   // scores -> softmax probs (in place)
__device__ float g_lg[2ull*BN*MN];   // log(ph + 1e-10)
__device__ float g_Sc[(size_t)BN*BN];
__device__ unsigned g_minkey;
__device__ float g_rowlog[BN];
__device__ float g_mse[256*4];

// ---------- helpers ----------
__device__ __forceinline__ unsigned sortkey(float v) {
    unsigned u = __float_as_uint(v);
    return (u & 0x80000000u) ? ~u : (u | 0x80000000u);
}
__device__ __forceinline__ float unsortkey(unsigned k) {
    return (k & 0x80000000u) ? __uint_as_float(k & 0x7FFFFFFFu)
                             : __uint_as_float(~k);
}
__device__ __forceinline__ ull packdi(float v, int idx) {
    return ((ull)sortkey(v) << 32) | (unsigned)idx;
}

// ---------- row norms: mode 0 -> g_Enorm, 1 -> g_xnorm0(+off), 2 -> g_xnormR from g_res ----------
__global__ __launch_bounds__(256) void k_rownorm(const float* __restrict__ Xin,
                                                 int nrows, int mode, int off) {
    int w = (blockIdx.x * 256 + threadIdx.x) >> 5;
    int lane = threadIdx.x & 31;
    if (w >= nrows) return;
    const float* X = (mode == 2) ? g_res : Xin;
    float* dst = (mode == 0) ? g_Enorm : ((mode == 1) ? g_xnorm0 : g_xnormR);
    float4 v = reinterpret_cast<const float4*>(X + (size_t)w * DN)[lane];
    float s = v.x*v.x + v.y*v.y + v.z*v.z + v.w*v.w;
    #pragma unroll
    for (int o = 16; o; o >>= 1) s += __shfl_xor_sync(0xFFFFFFFFu, s, o);
    if (lane == 0) dst[off + w] = s;
}

// ---------- init ----------
__global__ __launch_bounds__(256) void k_init(const float* __restrict__ pcf,
                                              const float* __restrict__ plm) {
    int stride = gridDim.x * 256;
    for (int i = blockIdx.x * 256 + threadIdx.x; i < QN; i += stride) {
        g_res[i] = (i < HALFQ) ? pcf[i] : plm[i - HALFQ];
        g_q[i] = 0.0f;
    }
    for (int i = blockIdx.x * 256 + threadIdx.x; i < KS*2*MN; i += stride)
        g_counts[i] = 0;
    if (blockIdx.x == 0 && threadIdx.x == 0) g_minkey = 0xFFFFFFFFu;
}

__global__ __launch_bounds__(256) void k_resetmin() {
    int i = blockIdx.x * 256 + threadIdx.x;
    if (i < 2*BN) g_min[i] = 0xFFFFFFFFFFFFFFFFull;
}

// ---------- argmin distance GEMM: grid (128 m-tiles, 64 b-tiles, 2 streams) ----------
__global__ __launch_bounds__(256) void k_argmin(const float* __restrict__ emb, int stage) {
    __shared__ __align__(16) float resS[64*65];
    __shared__ __align__(16) float eS[64*65];
    const int tid = threadIdx.x;
    const int tx = tid & 15, ty = tid >> 4;
    const int stream = blockIdx.z;
    const int b0 = blockIdx.y * 64;
    const int m0 = blockIdx.x * 64;
    const float* resp = g_res + (size_t)stream * HALFQ;
    const float* Ep = emb + (size_t)stage * MN * DN;
    const float* En = g_Enorm + stage * MN;

    float xn[4];
    #pragma unroll
    for (int i = 0; i < 4; i++) xn[i] = g_xnormR[stream*BN + b0 + 4*ty + i];

    float acc[4][4];
    #pragma unroll
    for (int i = 0; i < 4; i++)
        #pragma unroll
        for (int j = 0; j < 4; j++) acc[i][j] = 0.0f;

    for (int dc = 0; dc < 2; dc++) {
        #pragma unroll
        for (int k = 0; k < 16; k++) {
            int e = tid + 256*k; int r = e >> 6; int dd = e & 63;
            resS[r*65 + dd] = resp[(size_t)(b0 + r)*DN + dc*64 + dd];
            eS[r*65 + dd]   = Ep[(size_t)(m0 + r)*DN + dc*64 + dd];
        }
        __syncthreads();
        #pragma unroll
        for (int d = 0; d < 64; d++) {
            float a[4], bb[4];
            #pragma unroll
            for (int i = 0; i < 4; i++) a[i] = resS[(4*ty+i)*65 + d];
            #pragma unroll
            for (int j = 0; j < 4; j++) bb[j] = eS[(tx+16*j)*65 + d];
            #pragma unroll
            for (int i = 0; i < 4; i++)
                #pragma unroll
                for (int j = 0; j < 4; j++) acc[i][j] += a[i]*bb[j];
        }
        __syncthreads();
    }
    ull lb[4];
    #pragma unroll
    for (int i = 0; i < 4; i++) {
        float best = 3.4e38f; int bidx = 0;
        #pragma unroll
        for (int j = 0; j < 4; j++) {
            int mcol = m0 + tx + 16*j;
            float val = (En[mcol] + xn[i]) - 2.0f*acc[i][j];
            if (val < best) { best = val; bidx = mcol; }
        }
        lb[i] = packdi(best, bidx);
    }
    ull* red = (ull*)eS;
    #pragma unroll
    for (int i = 0; i < 4; i++) red[(4*ty+i)*16 + tx] = lb[i];
    __syncthreads();
    if (tid < 64) {
        ull kk = red[tid*16];
        #pragma unroll
        for (int t = 1; t < 16; t++) { ull c = red[tid*16 + t]; if (c < kk) kk = c; }
        atomicMin(&g_min[(size_t)stream*BN + b0 + tid], kk);
    }
}

// ---------- gather + residual/q update + histogram ----------
__global__ __launch_bounds__(256) void k_update(const float* __restrict__ emb, int stage) {
    int w = (blockIdx.x * 256 + threadIdx.x) >> 5;
    int lane = threadIdx.x & 31;
    if (w >= 2*BN) return;
    int stream = w >> 12; int b = w & (BN - 1);
    int idx = (int)(g_min[w] & 0xFFFFFFFFull);
    float4 e = reinterpret_cast<const float4*>(emb + ((size_t)stage*MN + idx)*DN)[lane];
    float4* qp = reinterpret_cast<float4*>(g_q + (size_t)w*DN);
    float4* rp = reinterpret_cast<float4*>(g_res + (size_t)w*DN);
    float4 q = qp[lane]; q.x += e.x; q.y += e.y; q.z += e.z; q.w += e.w; qp[lane] = q;
    float4 r = rp[lane]; r.x -= e.x; r.y -= e.y; r.z -= e.z; r.w -= e.w; rp[lane] = r;
    if (lane == 0) {
        g_idx[stream*BN*KS + b*KS + stage] = idx;
        atomicAdd(&g_counts[(stage*2 + stream)*MN + idx], 1);
    }
}

// ---------- cmcm scores: -sqrt(max(dist,0)) on ORIGINAL inputs vs last-stage E ----------
__global__ __launch_bounds__(256) void k_scores(const float* __restrict__ emb,
                                                const float* __restrict__ pcf,
                                                const float* __restrict__ plm) {
    __shared__ __align__(16) float xS[64*65];
    __shared__ __align__(16) float eS[64*65];
    const int tid = threadIdx.x;
    const int tx = tid & 15, ty = tid >> 4;
    const int stream = blockIdx.z;
    const int b0 = blockIdx.y * 64;
    const int m0 = blockIdx.x * 64;
    const float* Xp = (stream == 0) ? pcf : plm;
    const float* Ep = emb + (size_t)(KS-1) * MN * DN;
    const float* En = g_Enorm + (KS-1)*MN;

    float xn[4];
    #pragma unroll
    for (int i = 0; i < 4; i++) xn[i] = g_xnorm0[stream*BN + b0 + 4*ty + i];

    float acc[4][4];
    #pragma unroll
    for (int i = 0; i < 4; i++)
        #pragma unroll
        for (int j = 0; j < 4; j++) acc[i][j] = 0.0f;

    for (int dc = 0; dc < 2; dc++) {
        #pragma unroll
        for (int k = 0; k < 16; k++) {
            int e = tid + 256*k; int r = e >> 6; int dd = e & 63;
            xS[r*65 + dd] = Xp[(size_t)(b0 + r)*DN + dc*64 + dd];
            eS[r*65 + dd] = Ep[(size_t)(m0 + r)*DN + dc*64 + dd];
        }
        __syncthreads();
        #pragma unroll
        for (int d = 0; d < 64; d++) {
            float a[4], bb[4];
            #pragma unroll
            for (int i = 0; i < 4; i++) a[i] = xS[(4*ty+i)*65 + d];
            #pragma unroll
            for (int j = 0; j < 4; j++) bb[j] = eS[(tx+16*j)*65 + d];
            #pragma unroll
            for (int i = 0; i < 4; i++)
                #pragma unroll
                for (int j = 0; j < 4; j++) acc[i][j] += a[i]*bb[j];
        }
        __syncthreads();
    }
    #pragma unroll
    for (int j = 0; j < 4; j++) {
        int mcol = m0 + tx + 16*j;
        float en = En[mcol];
        #pragma unroll
        for (int i = 0; i < 4; i++) {
            float val = fmaxf((en + xn[i]) - 2.0f*acc[i][j], 0.0f);
            g_ph[(size_t)stream*BN*MN + (size_t)(b0 + 4*ty + i)*MN + mcol] = -sqrtf(val);
        }
    }
}

// ---------- row softmax + log ----------
__global__ __launch_bounds__(256) void k_softmax() {
    __shared__ __align__(16) float srow[MN];
    __shared__ float red[256];
    int b = blockIdx.x, s = blockIdx.y, tid = threadIdx.x;
    size_t base = (size_t)s*BN*MN + (size_t)b*MN;
    const float4* src = reinterpret_cast<const float4*>(g_ph + base);
    float mx = -3.4e38f;
    #pragma unroll
    for (int k = 0; k < 8; k++) {
        float4 v = src[tid + 256*k];
        reinterpret_cast<float4*>(srow)[tid + 256*k] = v;
        mx = fmaxf(mx, fmaxf(fmaxf(v.x, v.y), fmaxf(v.z, v.w)));
    }
    red[tid] = mx; __syncthreads();
    for (int o = 128; o > 0; o >>= 1) {
        if (tid < o) red[tid] = fmaxf(red[tid], red[tid + o]);
        __syncthreads();
    }
    mx = red[0]; __syncthreads();
    float sum = 0.0f;
    #pragma unroll
    for (int k = 0; k < 8; k++) {
        float4 v = reinterpret_cast<float4*>(srow)[tid + 256*k];
        v.x = expf(v.x - mx); v.y = expf(v.y - mx);
        v.z = expf(v.z - mx); v.w = expf(v.w - mx);
        reinterpret_cast<float4*>(srow)[tid + 256*k] = v;
        sum += v.x + v.y + v.z + v.w;
    }
    red[tid] = sum; __syncthreads();
    for (int o = 128; o > 0; o >>= 1) {
        if (tid < o) red[tid] = red[tid] + red[tid + o];
        __syncthreads();
    }
    sum = red[0];
    float4* dph = reinterpret_cast<float4*>(g_ph + base);
    float4* dlg = reinterpret_cast<float4*>(g_lg + base);
    #pragma unroll
    for (int k = 0; k < 8; k++) {
        float4 v = reinterpret_cast<float4*>(srow)[tid + 256*k];
        v.x /= sum; v.y /= sum; v.z /= sum; v.w /= sum;
        dph[tid + 256*k] = v;
        float4 l;
        l.x = logf(v.x + 1e-10f); l.y = logf(v.y + 1e-10f);
        l.z = logf(v.z + 1e-10f); l.w = logf(v.w + 1e-10f);
        dlg[tid + 256*k] = l;
    }
}

// ---------- Scode = Ppcf @ Lplm^T + Pplm @ Lpcf^T, fused global min ----------
__global__ __launch_bounds__(256) void k_scode() {
    __shared__ float sA1[64*33], sA2[64*33], sB1[64*33], sB2[64*33];
    __shared__ float red[256];
    const int tid = threadIdx.x;
    const int tx = tid & 15, ty = tid >> 4;
    const int i0 = blockIdx.y * 64, j0 = blockIdx.x * 64;
    const float* Ppcf = g_ph;
    const float* Pplm = g_ph + (size_t)BN*MN;
    const float* Lpcf = g_lg;
    const float* Lplm = g_lg + (size_t)BN*MN;

    float acc[4][4];
    #pragma unroll
    for (int i = 0; i < 4; i++)
        #pragma unroll
        for (int j = 0; j < 4; j++) acc[i][j] = 0.0f;

    const int lr = tid >> 3, lc = (tid & 7) * 4;
    for (int k0 = 0; k0 < MN; k0 += 32) {
        #pragma unroll
        for (int h = 0; h < 2; h++) {
            int row = lr + h*32;
            float4 v;
            v = *(const float4*)&Ppcf[(size_t)(i0+row)*MN + k0 + lc];
            sA1[row*33+lc] = v.x; sA1[row*33+lc+1] = v.y; sA1[row*33+lc+2] = v.z; sA1[row*33+lc+3] = v.w;
            v = *(const float4*)&Pplm[(size_t)(i0+row)*MN + k0 + lc];
            sA2[row*33+lc] = v.x; sA2[row*33+lc+1] = v.y; sA2[row*33+lc+2] = v.z; sA2[row*33+lc+3] = v.w;
            v = *(const float4*)&Lplm[(size_t)(j0+row)*MN + k0 + lc];
            sB1[row*33+lc] = v.x; sB1[row*33+lc+1] = v.y; sB1[row*33+lc+2] = v.z; sB1[row*33+lc+3] = v.w;
            v = *(const float4*)&Lpcf[(size_t)(j0+row)*MN + k0 + lc];
            sB2[row*33+lc] = v.x; sB2[row*33+lc+1] = v.y; sB2[row*33+lc+2] = v.z; sB2[row*33+lc+3] = v.w;
        }
        __syncthreads();
        #pragma unroll
        for (int kk = 0; kk < 32; kk++) {
            float a1[4], a2[4], b1[4], b2[4];
            #pragma unroll
            for (int i = 0; i < 4; i++) { a1[i] = sA1[(4*ty+i)*33+kk]; a2[i] = sA2[(4*ty+i)*33+kk]; }
            #pragma unroll
            for (int j = 0; j < 4; j++) { b1[j] = sB1[(tx+16*j)*33+kk]; b2[j] = sB2[(tx+16*j)*33+kk]; }
            #pragma unroll
            for (int i = 0; i < 4; i++)
                #pragma unroll
                for (int j = 0; j < 4; j++)
                    acc[i][j] += a1[i]*b1[j] + a2[i]*b2[j];
        }
        __syncthreads();
    }
    float lmin = 3.4e38f;
    #pragma unroll
    for (int i = 0; i < 4; i++)
        #pragma unroll
        for (int j = 0; j < 4; j++) {
            float v = acc[i][j];
            g_Sc[(size_t)(i0 + 4*ty + i)*BN + j0 + tx + 16*j] = v;
            lmin = fminf(lmin, v);
        }
    red[tid] = lmin; __syncthreads();
    for (int o = 128; o > 0; o >>= 1) {
        if (tid < o) red[tid] = fminf(red[tid], red[tid + o]);
        __syncthreads();
    }
    if (tid == 0) atomicMin(&g_minkey, sortkey(red[0]));
}

// ---------- per-row: log(diag(E)/(rowsum(E)+eps)), E = exp(Sc + MaxScode) ----------
__global__ __launch_bounds__(256) void k_rowratio() {
    __shared__ float red[256];
    int i = blockIdx.x, tid = threadIdx.x;
    float Mx = -unsortkey(g_minkey);   // MaxScode = -min(Sc)
    const float* row = g_Sc + (size_t)i * BN;
    float sum = 0.0f;
    #pragma unroll
    for (int k = 0; k < 16; k++) sum += expf(row[tid + 256*k] + Mx);
    red[tid] = sum; __syncthreads();
    for (int o = 128; o > 0; o >>= 1) {
        if (tid < o) red[tid] = red[tid] + red[tid + o];
        __syncthreads();
    }
    if (tid == 0) {
        float ratio = expf(row[i] + Mx) / (red[0] + 1e-5f);
        g_rowlog[i] = logf(ratio);
    }
}

// ---------- quantized = fl(x + fl(q - x)) ----------
__global__ __launch_bounds__(256) void k_quant(const float* __restrict__ pcf,
                                               const float* __restrict__ plm,
                                               float* __restrict__ out) {
    int e = blockIdx.x * 256 + threadIdx.x;
    if (e >= QN) return;
    float x = (e < HALFQ) ? pcf[e] : plm[e - HALFQ];
    float t = g_q[e] - x;
    out[e] = x + t;
}

// ---------- sem_ids as float ----------
__global__ __launch_bounds__(256) void k_ids(float* __restrict__ out) {
    int e = blockIdx.x * 256 + threadIdx.x;
    if (e < 2*BN*KS) out[OFF_IDS + e] = (float)g_idx[e];
}

// ---------- 4 MSE partial sums ----------
__global__ __launch_bounds__(256) void k_mse(const float* __restrict__ pcf,
                                             const float* __restrict__ plm,
                                             const float* __restrict__ out) {
    __shared__ float red[256];
    int tid = threadIdx.x, bid = blockIdx.x;
    float s[4] = {0.f, 0.f, 0.f, 0.f};
    #pragma unroll
    for (int k = 0; k < 8; k++) {
        int e = bid*2048 + k*256 + tid;
        float qp = out[e], qm = out[HALFQ + e];
        float xp = pcf[e], xm = plm[e];
        float d;
        d = xp - qp; s[0] += d*d;
        d = xp - qm; s[1] += d*d;
        d = xm - qm; s[2] += d*d;
        d = xm - qp; s[3] += d*d;
    }
    #pragma unroll
    for (int c = 0; c < 4; c++) {
        red[tid] = s[c]; __syncthreads();
        for (int o = 128; o > 0; o >>= 1) {
            if (tid < o) red[tid] = red[tid] + red[tid + o];
            __syncthreads();
        }
        if (tid == 0) g_mse[bid*4 + c] = red[0];
        __syncthreads();
    }
}

// ---------- perplexities ----------
__global__ __launch_bounds__(256) void k_perp(float* __restrict__ out) {
    __shared__ float red[256];
    int b = blockIdx.x, tid = threadIdx.x;
    int k = b >> 1, s = b & 1;
    const int* cnt = g_counts + (k*2 + s)*MN;
    float sum = 0.0f;
    #pragma unroll
    for (int t = 0; t < 32; t++) {
        float avg = (float)cnt[tid + 256*t] / (float)BN;
        sum += avg * logf(avg + 1e-10f);
    }
    red[tid] = sum; __syncthreads();
    for (int o = 128; o > 0; o >>= 1) {
        if (tid < o) red[tid] = red[tid] + red[tid + o];
        __syncthreads();
    }
    if (tid == 0) out[OFF_PERP + k*2 + s] = expf(-red[0]);
}

// ---------- final loss ----------
__global__ __launch_bounds__(256) void k_final(float* __restrict__ out) {
    __shared__ float red[256];
    int tid = threadIdx.x;
    float s = 0.0f;
    #pragma unroll
    for (int k = 0; k < 16; k++) s += g_rowlog[tid + 256*k];
    red[tid] = s; __syncthreads();
    for (int o = 128; o > 0; o >>= 1) {
        if (tid < o) red[tid] = red[tid] + red[tid + o];
        __syncthreads();
    }
    float Lc = -(red[0] / (float)BN);
    __syncthreads();
    float m[4];
    for (int c = 0; c < 4; c++) {
        red[tid] = g_mse[tid*4 + c]; __syncthreads();
        for (int o = 128; o > 0; o >>= 1) {
            if (tid < o) red[tid] = red[tid] + red[tid + o];
            __syncthreads();
        }
        m[c] = red[0] / (float)HALFQ;
        __syncthreads();
    }
    if (tid == 0) {
        float pcf_loss = 0.5f*m[0] + 0.25f*m[1];
        float plm_loss = 0.5f*m[2] + 0.25f*m[3];
        out[OFF_LOSS] = 0.5f*Lc + pcf_loss + plm_loss;
    }
}

// ---------- orchestration ----------
extern "C" void kernel_launch(void* const* d_in, const int* in_sizes, int n_in,
                              void* d_out, int out_size) {
    const float* pcf = (const float*)d_in[0];
    const float* plm = (const float*)d_in[1];
    const float* emb = (const float*)d_in[2];
    float* out = (float*)d_out;

    k_init<<<256, 256>>>(pcf, plm);
    k_rownorm<<<4096, 256>>>(emb, KS*MN, 0, 0);
    k_rownorm<<<512, 256>>>(pcf, BN, 1, 0);
    k_rownorm<<<512, 256>>>(plm, BN, 1, BN);

    for (int s = 0; s < KS; s++) {
        k_resetmin<<<32, 256>>>();
        k_rownorm<<<1024, 256>>>(nullptr, 2*BN, 2, 0);
        k_argmin<<<dim3(128, 64, 2), 256>>>(emb, s);
        k_update<<<1024, 256>>>(emb, s);
    }

    k_scores<<<dim3(128, 64, 2), 256>>>(emb, pcf, plm);
    k_softmax<<<dim3(BN, 2), 256>>>();
    k_scode<<<dim3(64, 64), 256>>>();
    k_rowratio<<<BN, 256>>>();

    k_quant<<<QN/256, 256>>>(pcf, plm, out);
    k_ids<<<(2*BN*KS)/256, 256>>>(out);
    k_mse<<<256, 256>>>(pcf, plm, out);
    k_perp<<<8, 256>>>(out);
    k_final<<<1, 256>>>(out);
}